// round 15
// baseline (speedup 1.0000x reference)
#include <cuda_runtime.h>
#include <cuda_bf16.h>
#include <cstdint>
#include <cstddef>

// ---------------------------------------------------------------------------
// VQ-VAE 1D forward, round 15: conv1 M=256 tile (8 warps), prevq fused into
// enc res1 epilogue.  Rest identical to R14 (410us base).
// ---------------------------------------------------------------------------
#define DEVBUF_N (16 * 64 * 1024)
__device__ float g_A[DEVBUF_N];
__device__ float g_B[DEVBUF_N];
__device__ float g_C[DEVBUF_N];
__device__ float g_P[4 * 16 * 32 * 2048];          // conv1 partials
__device__ __nv_bfloat16 g_Whi[32 * 3072];
__device__ __nv_bfloat16 g_Wlo[32 * 3072];
__device__ float g_enorm[512];

// Pre-split conv1 weights into bf16 hi/lo (once; same layout as w).
__global__ __launch_bounds__(256) void wprep_kernel(
    const float* __restrict__ w, __nv_bfloat16* __restrict__ whi,
    __nv_bfloat16* __restrict__ wlo)
{
    int i = blockIdx.x * 256 + threadIdx.x;
    if (i < 32 * 3072) {
        float v = w[i];
        __nv_bfloat16 h = __float2bfloat16(v);
        whi[i] = h;
        wlo[i] = __float2bfloat16(v - __bfloat162float(h));
    }
}

// mma.sync m16n8k16 row.col f32.bf16.bf16.f32 (sm_80+ baseline PTX)
#define MMA_BF16(d, a, b0, b1)                                               \
    asm volatile("mma.sync.aligned.m16n8k16.row.col.f32.bf16.bf16.f32 "      \
                 "{%0,%1,%2,%3}, {%4,%5,%6,%7}, {%8,%9}, {%0,%1,%2,%3};"     \
                 : "+f"((d)[0]), "+f"((d)[1]), "+f"((d)[2]), "+f"((d)[3])    \
                 : "r"((a)[0]), "r"((a)[1]), "r"((a)[2]), "r"((a)[3]),       \
                   "r"(b0), "r"(b1))

// ---------------------------------------------------------------------------
// conv1 via HMMA: 768->32, k=4, s=2, p=1.  Grid (8,16,4), 256 threads.
// Block: 256 t x 32 oc over 192 input channels (12 chunks of 16 ch = K64).
// 8 warps, warp owns 32 t-rows.  x smem [c][264 words], 257 used:
// word w = bf16x2 of positions 2*t0-1+2w, 2*t0+2w.
// ---------------------------------------------------------------------------
__global__ __launch_bounds__(256) void conv1_mma(
    const float* __restrict__ x, const __nv_bfloat16* __restrict__ whi_g,
    const __nv_bfloat16* __restrict__ wlo_g, float* __restrict__ part)
{
    __shared__ uint32_t xhi32[16 * 264];
    __shared__ uint32_t xlo32[16 * 264];
    __shared__ uint32_t whi32[32 * 36];
    __shared__ uint32_t wlo32[32 * 36];

    const int b   = blockIdx.y;
    const int t0  = blockIdx.x * 256;
    const int cz  = blockIdx.z;
    const int tid = threadIdx.x;
    const int wrp  = tid >> 5;
    const int lane = tid & 31;
    const int g    = lane >> 2;
    const int tig  = lane & 3;

    const int cs  = tid >> 4;         // staging channel 0..15
    const int ws0 = tid & 15;         // staging word base

    uint32_t rxh[17], rxl[17], rwh[4], rwl[4];

    // ---- prefetch + convert chunk 0 ----
    {
        const int c0 = cz * 192;
        const float* xrow = x + ((size_t)b * 768 + c0 + cs) * 4096;
        #pragma unroll
        for (int j = 0; j < 17; j++) {
            int w = ws0 + 16 * j;
            int pos = 2 * t0 - 1 + 2 * w;
            float v0 = (w < 257 && pos >= 0 && pos < 4096) ? xrow[pos] : 0.f;
            float v1 = (w < 257 && pos + 1 >= 0 && pos + 1 < 4096)
                           ? xrow[pos + 1] : 0.f;
            __nv_bfloat162 h2 = __floats2bfloat162_rn(v0, v1);
            __nv_bfloat162 l2 = __floats2bfloat162_rn(
                v0 - __bfloat162float(h2.x), v1 - __bfloat162float(h2.y));
            rxh[j] = *(uint32_t*)&h2;
            rxl[j] = *(uint32_t*)&l2;
        }
        #pragma unroll
        for (int j = 0; j < 4; j++) {
            int i = tid + 256 * j;
            int oc = i >> 5, kp = i & 31;
            rwh[j] = ((const uint32_t*)whi_g)[oc * 1536 + c0 * 2 + kp];
            rwl[j] = ((const uint32_t*)wlo_g)[oc * 1536 + c0 * 2 + kp];
        }
    }

    float D[4][8] = {};   // [ng][frag-set A 0..3 | frag-set B 4..7]

    for (int cc = 0; cc < 12; cc++) {
        __syncthreads();
        // ---- store staged words ----
        #pragma unroll
        for (int j = 0; j < 17; j++) {
            int w = ws0 + 16 * j;
            if (w < 257) {
                xhi32[cs * 264 + w] = rxh[j];
                xlo32[cs * 264 + w] = rxl[j];
            }
        }
        #pragma unroll
        for (int j = 0; j < 4; j++) {
            int i = tid + 256 * j;
            int oc = i >> 5, kp = i & 31;
            whi32[oc * 36 + kp] = rwh[j];
            wlo32[oc * 36 + kp] = rwl[j];
        }
        __syncthreads();

        // ---- prefetch + convert next chunk (hidden under MMA phase) ----
        if (cc < 11) {
            const int c0 = cz * 192 + (cc + 1) * 16;
            const float* xrow = x + ((size_t)b * 768 + c0 + cs) * 4096;
            #pragma unroll
            for (int j = 0; j < 17; j++) {
                int w = ws0 + 16 * j;
                int pos = 2 * t0 - 1 + 2 * w;
                float v0 = (w < 257 && pos >= 0 && pos < 4096) ? xrow[pos] : 0.f;
                float v1 = (w < 257 && pos + 1 >= 0 && pos + 1 < 4096)
                               ? xrow[pos + 1] : 0.f;
                __nv_bfloat162 h2 = __floats2bfloat162_rn(v0, v1);
                __nv_bfloat162 l2 = __floats2bfloat162_rn(
                    v0 - __bfloat162float(h2.x), v1 - __bfloat162float(h2.y));
                rxh[j] = *(uint32_t*)&h2;
                rxl[j] = *(uint32_t*)&l2;
            }
            #pragma unroll
            for (int j = 0; j < 4; j++) {
                int i = tid + 256 * j;
                int oc = i >> 5, kp = i & 31;
                rwh[j] = ((const uint32_t*)whi_g)[oc * 1536 + c0 * 2 + kp];
                rwl[j] = ((const uint32_t*)wlo_g)[oc * 1536 + c0 * 2 + kp];
            }
        }

        // ---- MMA phase ----
        #pragma unroll
        for (int ks = 0; ks < 4; ks++) {
            const int ic0 = ks * 4 + (tig >> 1);
            const int wA  = wrp * 32 + g + (tig & 1);
            uint32_t ahA[4], alA[4], ahB[4], alB[4];
            ahA[0] = xhi32[ic0 * 264 + wA];
            ahA[1] = xhi32[ic0 * 264 + wA + 8];
            ahA[2] = xhi32[(ic0 + 2) * 264 + wA];
            ahA[3] = xhi32[(ic0 + 2) * 264 + wA + 8];
            alA[0] = xlo32[ic0 * 264 + wA];
            alA[1] = xlo32[ic0 * 264 + wA + 8];
            alA[2] = xlo32[(ic0 + 2) * 264 + wA];
            alA[3] = xlo32[(ic0 + 2) * 264 + wA + 8];
            ahB[0] = xhi32[ic0 * 264 + wA + 16];
            ahB[1] = xhi32[ic0 * 264 + wA + 24];
            ahB[2] = xhi32[(ic0 + 2) * 264 + wA + 16];
            ahB[3] = xhi32[(ic0 + 2) * 264 + wA + 24];
            alB[0] = xlo32[ic0 * 264 + wA + 16];
            alB[1] = xlo32[ic0 * 264 + wA + 24];
            alB[2] = xlo32[(ic0 + 2) * 264 + wA + 16];
            alB[3] = xlo32[(ic0 + 2) * 264 + wA + 24];

            const int kw = ks * 8 + tig;
            #pragma unroll
            for (int ng = 0; ng < 4; ng++) {
                const int n = ng * 8 + g;
                uint32_t bh0 = whi32[n * 36 + kw];
                uint32_t bh1 = whi32[n * 36 + kw + 4];
                uint32_t bl0 = wlo32[n * 36 + kw];
                uint32_t bl1 = wlo32[n * 36 + kw + 4];
                MMA_BF16(&D[ng][0], ahA, bh0, bh1);
                MMA_BF16(&D[ng][0], alA, bh0, bh1);
                MMA_BF16(&D[ng][0], ahA, bl0, bl1);
                MMA_BF16(&D[ng][4], ahB, bh0, bh1);
                MMA_BF16(&D[ng][4], alB, bh0, bh1);
                MMA_BF16(&D[ng][4], ahB, bl0, bl1);
            }
        }
    }

    float* dst = part + (size_t)cz * (16 * 32 * 2048);
    const int ta = t0 + wrp * 32 + g;
    #pragma unroll
    for (int ng = 0; ng < 4; ng++) {
        const int oc = ng * 8 + 2 * tig;
        dst[((size_t)b * 32 + oc)     * 2048 + ta]      = D[ng][0];
        dst[((size_t)b * 32 + oc + 1) * 2048 + ta]      = D[ng][1];
        dst[((size_t)b * 32 + oc)     * 2048 + ta + 8]  = D[ng][2];
        dst[((size_t)b * 32 + oc + 1) * 2048 + ta + 8]  = D[ng][3];
        dst[((size_t)b * 32 + oc)     * 2048 + ta + 16] = D[ng][4];
        dst[((size_t)b * 32 + oc + 1) * 2048 + ta + 16] = D[ng][5];
        dst[((size_t)b * 32 + oc)     * 2048 + ta + 24] = D[ng][6];
        dst[((size_t)b * 32 + oc + 1) * 2048 + ta + 24] = D[ng][7];
    }
}

// ---------------------------------------------------------------------------
// Fused residual block (R7-proven) + optional prevq 1x1 epilogue.
// PREVQ epilogue is halo-free: the 1x1 acts on this tile's own 64 outputs.
// ---------------------------------------------------------------------------
template <bool PREVQ>
__global__ __launch_bounds__(256) void resblock(
    const float* __restrict__ in, const float* __restrict__ w1,
    const float* __restrict__ w2, const float* __restrict__ pqw,
    const float* __restrict__ pqb, float* __restrict__ out)
{
    extern __shared__ float sm[];
    float* xs  = sm;                         // [64][68], 66 used
    float* w1s = xs + 64 * 68;               // 6144
    float* w2s = w1s + 64 * 32 * 3;          // 2048
    float* hs  = w2s + 32 * 64;              // [32][66], 64 used
    float* ys  = hs + 32 * 66;               // PREVQ: res1 out [64][64]
    float* pqs = ys + (PREVQ ? 64 * 64 : 0); // PREVQ: [ic][oc] 4096

    const int tid = threadIdx.x;
    const int b   = blockIdx.y;
    const int t0  = blockIdx.x * 64;

    for (int i = tid; i < 64 * 66; i += 256) {
        int ic = i / 66;
        int p  = i - ic * 66;
        int g  = t0 - 1 + p;
        xs[ic * 68 + p] = (g >= 0 && g < 1024)
                              ? in[((size_t)b * 64 + ic) * 1024 + g] : 0.f;
    }
    for (int i = tid; i < 32 * 64 * 3; i += 256) {
        int oc = i / 192;
        int r  = i - oc * 192;
        int ic = r / 3;
        int k  = r - ic * 3;
        w1s[(ic * 32 + oc) * 3 + k] = w1[i];
    }
    for (int i = tid; i < 64 * 32; i += 256) {
        int oc = i >> 5;
        int ic = i & 31;
        w2s[ic * 64 + oc] = w2[i];
    }
    if (PREVQ) {
        for (int i = tid; i < 64 * 64; i += 256) {
            int oc = i >> 6;
            int ic = i & 63;
            pqs[ic * 64 + oc] = pqw[i];
        }
    }
    __syncthreads();

    const int tg  = tid & 15;
    const int ocg = tid >> 4;

    {
        float acc[2][4] = {};
        #pragma unroll 4
        for (int ic = 0; ic < 64; ic++) {
            float wk[2][3];
            #pragma unroll
            for (int m = 0; m < 2; m++)
                #pragma unroll
                for (int k = 0; k < 3; k++)
                    wk[m][k] = w1s[(ic * 32 + ocg * 2 + m) * 3 + k];
            #pragma unroll
            for (int j = 0; j < 4; j++) {
                int p = tg + 16 * j;
                float x0 = fmaxf(xs[ic * 68 + p],     0.f);
                float x1 = fmaxf(xs[ic * 68 + p + 1], 0.f);
                float x2 = fmaxf(xs[ic * 68 + p + 2], 0.f);
                #pragma unroll
                for (int m = 0; m < 2; m++) {
                    acc[m][j] = fmaf(wk[m][0], x0, acc[m][j]);
                    acc[m][j] = fmaf(wk[m][1], x1, acc[m][j]);
                    acc[m][j] = fmaf(wk[m][2], x2, acc[m][j]);
                }
            }
        }
        #pragma unroll
        for (int m = 0; m < 2; m++)
            #pragma unroll
            for (int j = 0; j < 4; j++)
                hs[(ocg * 2 + m) * 66 + tg + 16 * j] = acc[m][j];
    }
    __syncthreads();

    {
        float acc[4][4] = {};
        #pragma unroll 4
        for (int ic = 0; ic < 32; ic++) {
            float wk[4];
            #pragma unroll
            for (int m = 0; m < 4; m++)
                wk[m] = w2s[ic * 64 + ocg * 4 + m];
            #pragma unroll
            for (int j = 0; j < 4; j++) {
                float hv = fmaxf(hs[ic * 66 + tg + 16 * j], 0.f);
                #pragma unroll
                for (int m = 0; m < 4; m++)
                    acc[m][j] = fmaf(wk[m], hv, acc[m][j]);
            }
        }
        #pragma unroll
        for (int m = 0; m < 4; m++) {
            int oc = ocg * 4 + m;
            #pragma unroll
            for (int j = 0; j < 4; j++) {
                int p = tg + 16 * j;
                float v = xs[oc * 68 + p + 1] + acc[m][j];
                if (PREVQ) ys[oc * 64 + p] = v;
                else out[((size_t)b * 64 + oc) * 1024 + t0 + p] = v;
            }
        }
    }

    if (PREVQ) {
        __syncthreads();
        float acc[4][4];
        #pragma unroll
        for (int m = 0; m < 4; m++) {
            float bv = pqb[ocg * 4 + m];
            #pragma unroll
            for (int j = 0; j < 4; j++) acc[m][j] = bv;
        }
        #pragma unroll 4
        for (int ic = 0; ic < 64; ic++) {
            float wk[4];
            #pragma unroll
            for (int m = 0; m < 4; m++)
                wk[m] = pqs[ic * 64 + ocg * 4 + m];
            #pragma unroll
            for (int j = 0; j < 4; j++) {
                float yv = fmaxf(ys[ic * 64 + tg + 16 * j], 0.f);
                #pragma unroll
                for (int m = 0; m < 4; m++)
                    acc[m][j] = fmaf(wk[m], yv, acc[m][j]);
            }
        }
        #pragma unroll
        for (int m = 0; m < 4; m++) {
            int oc = ocg * 4 + m;
            #pragma unroll
            for (int j = 0; j < 4; j++)
                out[((size_t)b * 64 + oc) * 1024 + t0 + tg + 16 * j] = acc[m][j];
        }
    }
}

// ---------------------------------------------------------------------------
// Generic small conv.  RED4: input = relu(sum of 4 split-C partials + bias_in).
// ---------------------------------------------------------------------------
template <int CIN, int COUT, int K, int S, int P,
          bool PRE, bool POST, bool RES, bool BIAS, bool RED4>
__global__ __launch_bounds__(COUT * 4) void convk(
    const float* __restrict__ in, const float* __restrict__ w,
    const float* __restrict__ bias, const float* __restrict__ res,
    const float* __restrict__ bias_in,
    float* __restrict__ out, int Lin, int Lout)
{
    constexpr int TT = 64;
    constexpr int XW = S * TT + K - 1;
    constexpr int XWP = XW + 1;
    constexpr int NT = COUT * 4;
    constexpr size_t PSTRIDE = (size_t)16 * 32 * 2048;

    extern __shared__ float sm[];
    float* ws = sm;
    float* xs = sm + CIN * COUT * K;

    const int tid = threadIdx.x;
    const int b   = blockIdx.y;
    const int t0  = blockIdx.x * TT;
    const int p0  = t0 * S - P;

    for (int i = tid; i < CIN * COUT * K; i += NT) {
        int oc = i / (CIN * K);
        int r  = i - oc * (CIN * K);
        int ic = r / K;
        int k  = r - ic * K;
        ws[(ic * COUT + oc) * K + k] = w[i];
    }
    for (int i = tid; i < CIN * XW; i += NT) {
        int ic = i / XW;
        int l  = i - ic * XW;
        int pos = p0 + l;
        float v = 0.f;
        if (pos >= 0 && pos < Lin) {
            size_t base = ((size_t)b * CIN + ic) * Lin + pos;
            if (RED4) {
                v = in[base] + in[base + PSTRIDE]
                  + in[base + 2 * PSTRIDE] + in[base + 3 * PSTRIDE]
                  + bias_in[ic];
                v = fmaxf(v, 0.f);
            } else {
                v = in[base];
                if (PRE) v = fmaxf(v, 0.f);
            }
        }
        xs[ic * XWP + l] = v;
    }
    __syncthreads();

    const int tg  = tid & 15;
    const int ocg = tid >> 4;
    float acc[4][4] = {};

    #pragma unroll 4
    for (int ic = 0; ic < CIN; ic++) {
        float wk[4][K];
        #pragma unroll
        for (int m = 0; m < 4; m++)
            #pragma unroll
            for (int k = 0; k < K; k++)
                wk[m][k] = ws[(ic * COUT + ocg * 4 + m) * K + k];
        #pragma unroll
        for (int j = 0; j < 4; j++) {
            const float* xp = &xs[ic * XWP + S * (tg + 16 * j)];
            float xv[K];
            #pragma unroll
            for (int k = 0; k < K; k++) xv[k] = xp[k];
            #pragma unroll
            for (int m = 0; m < 4; m++)
                #pragma unroll
                for (int k = 0; k < K; k++)
                    acc[m][j] = fmaf(wk[m][k], xv[k], acc[m][j]);
        }
    }

    #pragma unroll
    for (int m = 0; m < 4; m++) {
        int oc = ocg * 4 + m;
        float bv = 0.f;
        if (BIAS) bv = bias[oc];
        #pragma unroll
        for (int j = 0; j < 4; j++) {
            int t = t0 + tg + 16 * j;
            size_t oi = ((size_t)b * COUT + oc) * Lout + t;
            float v = acc[m][j] + bv;
            if (RES) v += res[oi];
            if (POST) v = fmaxf(v, 0.f);
            out[oi] = v;
        }
    }
}

// ---------------------------------------------------------------------------
// ConvTranspose1d (R1-proven).
// ---------------------------------------------------------------------------
template <int CIN, int COUT, bool PRE, bool POST>
__global__ __launch_bounds__(COUT * 4) void tconv(
    const float* __restrict__ in, const float* __restrict__ w,
    const float* __restrict__ bias, float* __restrict__ out,
    int Lin, int Lout)
{
    constexpr int NT = COUT * 4;
    __shared__ __align__(16) float ws[CIN * COUT * 4];
    __shared__ float xs[CIN * 35];

    const int tid = threadIdx.x;
    const int b   = blockIdx.y;
    const int t0  = blockIdx.x * 64;
    const int xbase = (t0 >> 1) - 1;

    for (int i = tid; i < CIN * COUT * 4; i += NT) ws[i] = w[i];
    for (int i = tid; i < CIN * 34; i += NT) {
        int ic = i / 34;
        int l  = i - ic * 34;
        int pos = xbase + l;
        float v = (pos >= 0 && pos < Lin)
                      ? in[((size_t)b * CIN + ic) * Lin + pos] : 0.f;
        if (PRE) v = fmaxf(v, 0.f);
        xs[ic * 35 + l] = v;
    }
    __syncthreads();

    const int tg  = tid & 15;
    const int ocg = tid >> 4;
    float acc[4][4] = {};

    #pragma unroll 4
    for (int ic = 0; ic < CIN; ic++) {
        float wk[4][4];
        #pragma unroll
        for (int m = 0; m < 4; m++) {
            float4 f = ((const float4*)ws)[ic * COUT + ocg * 4 + m];
            wk[m][0] = f.x; wk[m][1] = f.y; wk[m][2] = f.z; wk[m][3] = f.w;
        }
        #pragma unroll
        for (int j = 0; j < 4; j++) {
            int tl = tg + 16 * j;
            #pragma unroll
            for (int k = 0; k < 4; k++) {
                int e = tl + 1 - k;
                if (!(e & 1)) {
                    float xv = xs[ic * 35 + (e >> 1) + 1];
                    #pragma unroll
                    for (int m = 0; m < 4; m++)
                        acc[m][j] = fmaf(wk[m][k], xv, acc[m][j]);
                }
            }
        }
    }

    #pragma unroll
    for (int m = 0; m < 4; m++) {
        int oc = ocg * 4 + m;
        float bv = bias[oc];
        #pragma unroll
        for (int j = 0; j < 4; j++) {
            int t = t0 + tg + 16 * j;
            float v = acc[m][j] + bv;
            if (POST) v = fmaxf(v, 0.f);
            out[((size_t)b * COUT + oc) * Lout + t] = v;
        }
    }
}

// ---------------------------------------------------------------------------
__global__ void enorm_kernel(const float* __restrict__ emb, float* __restrict__ en)
{
    int i = blockIdx.x * blockDim.x + threadIdx.x;
    if (i < 512) {
        float s = 0.f;
        #pragma unroll
        for (int d = 0; d < 64; d++) {
            float v = emb[i * 64 + d];
            s = fmaf(v, v, s);
        }
        en[i] = s;
    }
}

// ---------------------------------------------------------------------------
// VQ v3 (R6-proven).
// ---------------------------------------------------------------------------
__global__ __launch_bounds__(256) void vq_kernel(
    const float* __restrict__ z, const float* __restrict__ emb,
    const float* __restrict__ enorm, float* __restrict__ q)
{
    const int b    = blockIdx.y;
    const int wid  = threadIdx.x >> 5;
    const int lane = threadIdx.x & 31;
    const int t    = blockIdx.x * 32 + lane;

    float4 v[16];
    #pragma unroll
    for (int d = 0; d < 16; d++) {
        v[d].x = z[((size_t)b * 64 + 4 * d + 0) * 1024 + t];
        v[d].y = z[((size_t)b * 64 + 4 * d + 1) * 1024 + t];
        v[d].z = z[((size_t)b * 64 + 4 * d + 2) * 1024 + t];
        v[d].w = z[((size_t)b * 64 + 4 * d + 3) * 1024 + t];
    }

    __shared__ __align__(16) float es[64 * 64];
    __shared__ float rbest[8][32];
    __shared__ int   ridx[8][32];
    __shared__ int   win[32];

    float best = 3.4e38f;
    int bi = 0;

    for (int c0 = 0; c0 < 512; c0 += 64) {
        __syncthreads();
        for (int i = threadIdx.x; i < 1024; i += 256)
            ((float4*)es)[i] = ((const float4*)(emb + (size_t)c0 * 64))[i];
        __syncthreads();
        #pragma unroll
        for (int i = 0; i < 8; i++) {
            int cl = wid * 8 + i;
            const float4* e4 = (const float4*)&es[cl * 64];
            float s0 = 0.f, s1 = 0.f, s2 = 0.f, s3 = 0.f;
            #pragma unroll
            for (int d = 0; d < 16; d++) {
                float4 e = e4[d];
                s0 = fmaf(v[d].x, e.x, s0);
                s1 = fmaf(v[d].y, e.y, s1);
                s2 = fmaf(v[d].z, e.z, s2);
                s3 = fmaf(v[d].w, e.w, s3);
            }
            float dist = enorm[c0 + cl] - 2.f * ((s0 + s1) + (s2 + s3));
            int ci = c0 + cl;
            if (dist < best || (dist == best && ci < bi)) {
                best = dist; bi = ci;
            }
        }
    }

    rbest[wid][lane] = best;
    ridx[wid][lane]  = bi;
    __syncthreads();

    if (wid == 0) {
        float wb = rbest[0][lane];
        int   wi = ridx[0][lane];
        #pragma unroll
        for (int w = 1; w < 8; w++) {
            float ob = rbest[w][lane];
            int   oi = ridx[w][lane];
            if (ob < wb || (ob == wb && oi < wi)) { wb = ob; wi = oi; }
        }
        win[lane] = wi;
    }
    __syncthreads();

    const int widx = win[lane];
    #pragma unroll
    for (int i = 0; i < 8; i++) {
        int d = wid * 8 + i;
        q[((size_t)b * 64 + d) * 1024 + t] = __ldg(&emb[widx * 64 + d]);
    }
}

// ---------------------------------------------------------------------------
template <int CIN, int COUT, int K, int S, int P,
          bool PRE, bool POST, bool RES, bool BIAS, bool RED4>
static void launch_convk(const float* in, const float* w, const float* bias,
                         const float* res, const float* bias_in,
                         float* out, int Lin, int Lout)
{
    constexpr int TT = 64;
    constexpr int XW = S * TT + K - 1;
    constexpr int XWP = XW + 1;
    constexpr int NT = COUT * 4;
    size_t smem = (size_t)(CIN * COUT * K + CIN * XWP) * sizeof(float);
    auto kern = convk<CIN, COUT, K, S, P, PRE, POST, RES, BIAS, RED4>;
    cudaFuncSetAttribute(kern, cudaFuncAttributeMaxDynamicSharedMemorySize,
                         (int)smem);
    kern<<<dim3(Lout / TT, 16), NT, smem>>>(in, w, bias, res, bias_in, out,
                                            Lin, Lout);
}

template <bool PREVQ>
static void launch_resblock(const float* in, const float* w1, const float* w2,
                            const float* pqw, const float* pqb, float* out)
{
    size_t base = (size_t)(64 * 68 + 64 * 32 * 3 + 32 * 64 + 32 * 66);
    size_t smem = (base + (PREVQ ? (64 * 64 + 64 * 64) : 0)) * sizeof(float);
    auto kern = resblock<PREVQ>;
    cudaFuncSetAttribute(kern, cudaFuncAttributeMaxDynamicSharedMemorySize,
                         (int)smem);
    kern<<<dim3(16, 16), 256, smem>>>(in, w1, w2, pqw, pqb, out);
}

extern "C" void kernel_launch(void* const* d_in, const int* in_sizes, int n_in,
                              void* d_out, int out_size)
{
    (void)in_sizes; (void)n_in; (void)out_size;

    const float* x       = (const float*)d_in[0];
    const float* enc_w1  = (const float*)d_in[1];
    const float* enc_b1  = (const float*)d_in[2];
    const float* enc_w2  = (const float*)d_in[3];
    const float* enc_b2  = (const float*)d_in[4];
    const float* enc_w3  = (const float*)d_in[5];
    const float* enc_b3  = (const float*)d_in[6];
    const float* e_r0w1  = (const float*)d_in[7];
    const float* e_r0w2  = (const float*)d_in[8];
    const float* e_r1w1  = (const float*)d_in[9];
    const float* e_r1w2  = (const float*)d_in[10];
    const float* prevq_w = (const float*)d_in[11];
    const float* prevq_b = (const float*)d_in[12];
    const float* emb     = (const float*)d_in[13];
    const float* dec_w1  = (const float*)d_in[14];
    const float* dec_b1  = (const float*)d_in[15];
    const float* d_r0w1  = (const float*)d_in[16];
    const float* d_r0w2  = (const float*)d_in[17];
    const float* d_r1w1  = (const float*)d_in[18];
    const float* d_r1w2  = (const float*)d_in[19];
    const float* dect1_w = (const float*)d_in[20];
    const float* dect1_b = (const float*)d_in[21];
    const float* dect2_w = (const float*)d_in[22];
    const float* dect2_b = (const float*)d_in[23];
    float* out = (float*)d_out;

    float *A, *B, *C, *PP, *EN;
    __nv_bfloat16 *WHI, *WLO;
    cudaGetSymbolAddress((void**)&A,   g_A);
    cudaGetSymbolAddress((void**)&B,   g_B);
    cudaGetSymbolAddress((void**)&C,   g_C);
    cudaGetSymbolAddress((void**)&PP,  g_P);
    cudaGetSymbolAddress((void**)&WHI, g_Whi);
    cudaGetSymbolAddress((void**)&WLO, g_Wlo);
    cudaGetSymbolAddress((void**)&EN,  g_enorm);

    // enorm(1), wprep(2), conv1(3), conv2(4 = ncu target)
    enorm_kernel<<<1, 512>>>(emb, EN);
    wprep_kernel<<<384, 256>>>(enc_w1, WHI, WLO);

    conv1_mma<<<dim3(8, 16, 4), 256>>>(x, WHI, WLO, PP);

    launch_convk<32, 64, 4, 2, 1, false, true,  false, true,  true >(
        PP, enc_w2, enc_b2, nullptr, enc_b1, B, 2048, 1024);
    launch_convk<64, 64, 3, 1, 1, false, false, false, true,  false>(
        B, enc_w3, enc_b3, nullptr, nullptr, C, 1024, 1024);
    // Encoder residual stack; res1 carries the prevq epilogue -> B = z
    launch_resblock<false>(C, e_r0w1, e_r0w2, nullptr, nullptr, A);
    launch_resblock<true >(A, e_r1w1, e_r1w2, prevq_w, prevq_b, B);
    // VQ
    vq_kernel<<<dim3(32, 16), 256>>>(B, emb, EN, A);            // A = q
    // Decoder
    launch_convk<64, 64, 3, 1, 1, false, false, false, true,  false>(
        A, dec_w1, dec_b1, nullptr, nullptr, B, 1024, 1024);
    launch_resblock<false>(B, d_r0w1, d_r0w2, nullptr, nullptr, A);
    launch_resblock<false>(A, d_r1w1, d_r1w2, nullptr, nullptr, B);
    // Transposed convs
    tconv<64, 32, true,  true ><<<dim3(32, 16), 128>>>(B, dect1_w, dect1_b, C,   1024, 2048);
    tconv<32, 64, false, false><<<dim3(64, 16), 256>>>(C, dect2_w, dect2_b, out, 2048, 4096);
}

// round 16
// speedup vs baseline: 1.0629x; 1.0629x over previous
#include <cuda_runtime.h>
#include <cuda_bf16.h>
#include <cstdint>
#include <cstddef>

// ---------------------------------------------------------------------------
// VQ-VAE 1D forward, round 16: R14 conv1 (M=128, proven) + prevq-fused
// resblock (from R15).  Everything else identical to R14 (410us base).
// ---------------------------------------------------------------------------
#define DEVBUF_N (16 * 64 * 1024)
__device__ float g_A[DEVBUF_N];
__device__ float g_B[DEVBUF_N];
__device__ float g_C[DEVBUF_N];
__device__ float g_P[4 * 16 * 32 * 2048];          // conv1 partials
__device__ __nv_bfloat16 g_Whi[32 * 3072];
__device__ __nv_bfloat16 g_Wlo[32 * 3072];
__device__ float g_enorm[512];

// Pre-split conv1 weights into bf16 hi/lo (once; same layout as w).
__global__ __launch_bounds__(256) void wprep_kernel(
    const float* __restrict__ w, __nv_bfloat16* __restrict__ whi,
    __nv_bfloat16* __restrict__ wlo)
{
    int i = blockIdx.x * 256 + threadIdx.x;
    if (i < 32 * 3072) {
        float v = w[i];
        __nv_bfloat16 h = __float2bfloat16(v);
        whi[i] = h;
        wlo[i] = __float2bfloat16(v - __bfloat162float(h));
    }
}

// mma.sync m16n8k16 row.col f32.bf16.bf16.f32 (sm_80+ baseline PTX)
#define MMA_BF16(d, a, b0, b1)                                               \
    asm volatile("mma.sync.aligned.m16n8k16.row.col.f32.bf16.bf16.f32 "      \
                 "{%0,%1,%2,%3}, {%4,%5,%6,%7}, {%8,%9}, {%0,%1,%2,%3};"     \
                 : "+f"((d)[0]), "+f"((d)[1]), "+f"((d)[2]), "+f"((d)[3])    \
                 : "r"((a)[0]), "r"((a)[1]), "r"((a)[2]), "r"((a)[3]),       \
                   "r"(b0), "r"(b1))

// ---------------------------------------------------------------------------
// conv1 via HMMA (R14-proven): 768->32, k=4, s=2, p=1.  Grid (16,16,4),
// 128 threads.  Block: 128 t x 32 oc over 192 input channels (12 chunks of
// 16 ch = K64).  Warp w owns 32 t-rows.  x smem [c][136 words], 129 used.
// ---------------------------------------------------------------------------
__global__ __launch_bounds__(128) void conv1_mma(
    const float* __restrict__ x, const __nv_bfloat16* __restrict__ whi_g,
    const __nv_bfloat16* __restrict__ wlo_g, float* __restrict__ part)
{
    __shared__ uint32_t xhi32[16 * 136];
    __shared__ uint32_t xlo32[16 * 136];
    __shared__ uint32_t whi32[32 * 36];
    __shared__ uint32_t wlo32[32 * 36];

    const int b   = blockIdx.y;
    const int t0  = blockIdx.x * 128;
    const int cz  = blockIdx.z;
    const int tid = threadIdx.x;
    const int wrp  = tid >> 5;
    const int lane = tid & 31;
    const int g    = lane >> 2;
    const int tig  = lane & 3;

    const int cs  = tid >> 3;         // staging channel 0..15
    const int ws0 = tid & 7;          // staging word base

    uint32_t rxh[17], rxl[17], rwh[8], rwl[8];

    // ---- prefetch + convert chunk 0 ----
    {
        const int c0 = cz * 192;
        const float* xrow = x + ((size_t)b * 768 + c0 + cs) * 4096;
        #pragma unroll
        for (int j = 0; j < 17; j++) {
            int w = ws0 + 8 * j;
            int pos = 2 * t0 - 1 + 2 * w;
            float v0 = (w < 129 && pos >= 0 && pos < 4096) ? xrow[pos] : 0.f;
            float v1 = (w < 129 && pos + 1 >= 0 && pos + 1 < 4096)
                           ? xrow[pos + 1] : 0.f;
            __nv_bfloat162 h2 = __floats2bfloat162_rn(v0, v1);
            __nv_bfloat162 l2 = __floats2bfloat162_rn(
                v0 - __bfloat162float(h2.x), v1 - __bfloat162float(h2.y));
            rxh[j] = *(uint32_t*)&h2;
            rxl[j] = *(uint32_t*)&l2;
        }
        #pragma unroll
        for (int j = 0; j < 8; j++) {
            int i = tid + 128 * j;
            int oc = i >> 5, kp = i & 31;
            rwh[j] = ((const uint32_t*)whi_g)[oc * 1536 + c0 * 2 + kp];
            rwl[j] = ((const uint32_t*)wlo_g)[oc * 1536 + c0 * 2 + kp];
        }
    }

    float D[4][8] = {};   // [ng][frag-set A 0..3 | frag-set B 4..7]

    for (int cc = 0; cc < 12; cc++) {
        __syncthreads();
        // ---- store staged words ----
        #pragma unroll
        for (int j = 0; j < 17; j++) {
            int w = ws0 + 8 * j;
            if (w < 129) {
                xhi32[cs * 136 + w] = rxh[j];
                xlo32[cs * 136 + w] = rxl[j];
            }
        }
        #pragma unroll
        for (int j = 0; j < 8; j++) {
            int i = tid + 128 * j;
            int oc = i >> 5, kp = i & 31;
            whi32[oc * 36 + kp] = rwh[j];
            wlo32[oc * 36 + kp] = rwl[j];
        }
        __syncthreads();

        // ---- prefetch + convert next chunk (hidden under MMA phase) ----
        if (cc < 11) {
            const int c0 = cz * 192 + (cc + 1) * 16;
            const float* xrow = x + ((size_t)b * 768 + c0 + cs) * 4096;
            #pragma unroll
            for (int j = 0; j < 17; j++) {
                int w = ws0 + 8 * j;
                int pos = 2 * t0 - 1 + 2 * w;
                float v0 = (w < 129 && pos >= 0 && pos < 4096) ? xrow[pos] : 0.f;
                float v1 = (w < 129 && pos + 1 >= 0 && pos + 1 < 4096)
                               ? xrow[pos + 1] : 0.f;
                __nv_bfloat162 h2 = __floats2bfloat162_rn(v0, v1);
                __nv_bfloat162 l2 = __floats2bfloat162_rn(
                    v0 - __bfloat162float(h2.x), v1 - __bfloat162float(h2.y));
                rxh[j] = *(uint32_t*)&h2;
                rxl[j] = *(uint32_t*)&l2;
            }
            #pragma unroll
            for (int j = 0; j < 8; j++) {
                int i = tid + 128 * j;
                int oc = i >> 5, kp = i & 31;
                rwh[j] = ((const uint32_t*)whi_g)[oc * 1536 + c0 * 2 + kp];
                rwl[j] = ((const uint32_t*)wlo_g)[oc * 1536 + c0 * 2 + kp];
            }
        }

        // ---- MMA phase ----
        #pragma unroll
        for (int ks = 0; ks < 4; ks++) {
            const int ic0 = ks * 4 + (tig >> 1);
            const int wA  = wrp * 32 + g + (tig & 1);
            uint32_t ahA[4], alA[4], ahB[4], alB[4];
            ahA[0] = xhi32[ic0 * 136 + wA];
            ahA[1] = xhi32[ic0 * 136 + wA + 8];
            ahA[2] = xhi32[(ic0 + 2) * 136 + wA];
            ahA[3] = xhi32[(ic0 + 2) * 136 + wA + 8];
            alA[0] = xlo32[ic0 * 136 + wA];
            alA[1] = xlo32[ic0 * 136 + wA + 8];
            alA[2] = xlo32[(ic0 + 2) * 136 + wA];
            alA[3] = xlo32[(ic0 + 2) * 136 + wA + 8];
            ahB[0] = xhi32[ic0 * 136 + wA + 16];
            ahB[1] = xhi32[ic0 * 136 + wA + 24];
            ahB[2] = xhi32[(ic0 + 2) * 136 + wA + 16];
            ahB[3] = xhi32[(ic0 + 2) * 136 + wA + 24];
            alB[0] = xlo32[ic0 * 136 + wA + 16];
            alB[1] = xlo32[ic0 * 136 + wA + 24];
            alB[2] = xlo32[(ic0 + 2) * 136 + wA + 16];
            alB[3] = xlo32[(ic0 + 2) * 136 + wA + 24];

            const int kw = ks * 8 + tig;
            #pragma unroll
            for (int ng = 0; ng < 4; ng++) {
                const int n = ng * 8 + g;
                uint32_t bh0 = whi32[n * 36 + kw];
                uint32_t bh1 = whi32[n * 36 + kw + 4];
                uint32_t bl0 = wlo32[n * 36 + kw];
                uint32_t bl1 = wlo32[n * 36 + kw + 4];
                MMA_BF16(&D[ng][0], ahA, bh0, bh1);
                MMA_BF16(&D[ng][0], alA, bh0, bh1);
                MMA_BF16(&D[ng][0], ahA, bl0, bl1);
                MMA_BF16(&D[ng][4], ahB, bh0, bh1);
                MMA_BF16(&D[ng][4], alB, bh0, bh1);
                MMA_BF16(&D[ng][4], ahB, bl0, bl1);
            }
        }
    }

    float* dst = part + (size_t)cz * (16 * 32 * 2048);
    const int ta = t0 + wrp * 32 + g;
    #pragma unroll
    for (int ng = 0; ng < 4; ng++) {
        const int oc = ng * 8 + 2 * tig;
        dst[((size_t)b * 32 + oc)     * 2048 + ta]      = D[ng][0];
        dst[((size_t)b * 32 + oc + 1) * 2048 + ta]      = D[ng][1];
        dst[((size_t)b * 32 + oc)     * 2048 + ta + 8]  = D[ng][2];
        dst[((size_t)b * 32 + oc + 1) * 2048 + ta + 8]  = D[ng][3];
        dst[((size_t)b * 32 + oc)     * 2048 + ta + 16] = D[ng][4];
        dst[((size_t)b * 32 + oc + 1) * 2048 + ta + 16] = D[ng][5];
        dst[((size_t)b * 32 + oc)     * 2048 + ta + 24] = D[ng][6];
        dst[((size_t)b * 32 + oc + 1) * 2048 + ta + 24] = D[ng][7];
    }
}

// ---------------------------------------------------------------------------
// Fused residual block (R7-proven) + optional prevq 1x1 epilogue (halo-free).
// ---------------------------------------------------------------------------
template <bool PREVQ>
__global__ __launch_bounds__(256) void resblock(
    const float* __restrict__ in, const float* __restrict__ w1,
    const float* __restrict__ w2, const float* __restrict__ pqw,
    const float* __restrict__ pqb, float* __restrict__ out)
{
    extern __shared__ float sm[];
    float* xs  = sm;                         // [64][68], 66 used
    float* w1s = xs + 64 * 68;
    float* w2s = w1s + 64 * 32 * 3;
    float* hs  = w2s + 32 * 64;              // [32][66], 64 used
    float* ys  = hs + 32 * 66;               // PREVQ: res1 out [64][64]
    float* pqs = ys + (PREVQ ? 64 * 64 : 0); // PREVQ: [ic][oc]

    const int tid = threadIdx.x;
    const int b   = blockIdx.y;
    const int t0  = blockIdx.x * 64;

    for (int i = tid; i < 64 * 66; i += 256) {
        int ic = i / 66;
        int p  = i - ic * 66;
        int g  = t0 - 1 + p;
        xs[ic * 68 + p] = (g >= 0 && g < 1024)
                              ? in[((size_t)b * 64 + ic) * 1024 + g] : 0.f;
    }
    for (int i = tid; i < 32 * 64 * 3; i += 256) {
        int oc = i / 192;
        int r  = i - oc * 192;
        int ic = r / 3;
        int k  = r - ic * 3;
        w1s[(ic * 32 + oc) * 3 + k] = w1[i];
    }
    for (int i = tid; i < 64 * 32; i += 256) {
        int oc = i >> 5;
        int ic = i & 31;
        w2s[ic * 64 + oc] = w2[i];
    }
    if (PREVQ) {
        for (int i = tid; i < 64 * 64; i += 256) {
            int oc = i >> 6;
            int ic = i & 63;
            pqs[ic * 64 + oc] = pqw[i];
        }
    }
    __syncthreads();

    const int tg  = tid & 15;
    const int ocg = tid >> 4;

    {
        float acc[2][4] = {};
        #pragma unroll 4
        for (int ic = 0; ic < 64; ic++) {
            float wk[2][3];
            #pragma unroll
            for (int m = 0; m < 2; m++)
                #pragma unroll
                for (int k = 0; k < 3; k++)
                    wk[m][k] = w1s[(ic * 32 + ocg * 2 + m) * 3 + k];
            #pragma unroll
            for (int j = 0; j < 4; j++) {
                int p = tg + 16 * j;
                float x0 = fmaxf(xs[ic * 68 + p],     0.f);
                float x1 = fmaxf(xs[ic * 68 + p + 1], 0.f);
                float x2 = fmaxf(xs[ic * 68 + p + 2], 0.f);
                #pragma unroll
                for (int m = 0; m < 2; m++) {
                    acc[m][j] = fmaf(wk[m][0], x0, acc[m][j]);
                    acc[m][j] = fmaf(wk[m][1], x1, acc[m][j]);
                    acc[m][j] = fmaf(wk[m][2], x2, acc[m][j]);
                }
            }
        }
        #pragma unroll
        for (int m = 0; m < 2; m++)
            #pragma unroll
            for (int j = 0; j < 4; j++)
                hs[(ocg * 2 + m) * 66 + tg + 16 * j] = acc[m][j];
    }
    __syncthreads();

    {
        float acc[4][4] = {};
        #pragma unroll 4
        for (int ic = 0; ic < 32; ic++) {
            float wk[4];
            #pragma unroll
            for (int m = 0; m < 4; m++)
                wk[m] = w2s[ic * 64 + ocg * 4 + m];
            #pragma unroll
            for (int j = 0; j < 4; j++) {
                float hv = fmaxf(hs[ic * 66 + tg + 16 * j], 0.f);
                #pragma unroll
                for (int m = 0; m < 4; m++)
                    acc[m][j] = fmaf(wk[m], hv, acc[m][j]);
            }
        }
        #pragma unroll
        for (int m = 0; m < 4; m++) {
            int oc = ocg * 4 + m;
            #pragma unroll
            for (int j = 0; j < 4; j++) {
                int p = tg + 16 * j;
                float v = xs[oc * 68 + p + 1] + acc[m][j];
                if (PREVQ) ys[oc * 64 + p] = v;
                else out[((size_t)b * 64 + oc) * 1024 + t0 + p] = v;
            }
        }
    }

    if (PREVQ) {
        __syncthreads();
        float acc[4][4];
        #pragma unroll
        for (int m = 0; m < 4; m++) {
            float bv = pqb[ocg * 4 + m];
            #pragma unroll
            for (int j = 0; j < 4; j++) acc[m][j] = bv;
        }
        #pragma unroll 4
        for (int ic = 0; ic < 64; ic++) {
            float wk[4];
            #pragma unroll
            for (int m = 0; m < 4; m++)
                wk[m] = pqs[ic * 64 + ocg * 4 + m];
            #pragma unroll
            for (int j = 0; j < 4; j++) {
                float yv = fmaxf(ys[ic * 64 + tg + 16 * j], 0.f);
                #pragma unroll
                for (int m = 0; m < 4; m++)
                    acc[m][j] = fmaf(wk[m], yv, acc[m][j]);
            }
        }
        #pragma unroll
        for (int m = 0; m < 4; m++) {
            int oc = ocg * 4 + m;
            #pragma unroll
            for (int j = 0; j < 4; j++)
                out[((size_t)b * 64 + oc) * 1024 + t0 + tg + 16 * j] = acc[m][j];
        }
    }
}

// ---------------------------------------------------------------------------
// Generic small conv.  RED4: input = relu(sum of 4 split-C partials + bias_in).
// ---------------------------------------------------------------------------
template <int CIN, int COUT, int K, int S, int P,
          bool PRE, bool POST, bool RES, bool BIAS, bool RED4>
__global__ __launch_bounds__(COUT * 4) void convk(
    const float* __restrict__ in, const float* __restrict__ w,
    const float* __restrict__ bias, const float* __restrict__ res,
    const float* __restrict__ bias_in,
    float* __restrict__ out, int Lin, int Lout)
{
    constexpr int TT = 64;
    constexpr int XW = S * TT + K - 1;
    constexpr int XWP = XW + 1;
    constexpr int NT = COUT * 4;
    constexpr size_t PSTRIDE = (size_t)16 * 32 * 2048;

    extern __shared__ float sm[];
    float* ws = sm;
    float* xs = sm + CIN * COUT * K;

    const int tid = threadIdx.x;
    const int b   = blockIdx.y;
    const int t0  = blockIdx.x * TT;
    const int p0  = t0 * S - P;

    for (int i = tid; i < CIN * COUT * K; i += NT) {
        int oc = i / (CIN * K);
        int r  = i - oc * (CIN * K);
        int ic = r / K;
        int k  = r - ic * K;
        ws[(ic * COUT + oc) * K + k] = w[i];
    }
    for (int i = tid; i < CIN * XW; i += NT) {
        int ic = i / XW;
        int l  = i - ic * XW;
        int pos = p0 + l;
        float v = 0.f;
        if (pos >= 0 && pos < Lin) {
            size_t base = ((size_t)b * CIN + ic) * Lin + pos;
            if (RED4) {
                v = in[base] + in[base + PSTRIDE]
                  + in[base + 2 * PSTRIDE] + in[base + 3 * PSTRIDE]
                  + bias_in[ic];
                v = fmaxf(v, 0.f);
            } else {
                v = in[base];
                if (PRE) v = fmaxf(v, 0.f);
            }
        }
        xs[ic * XWP + l] = v;
    }
    __syncthreads();

    const int tg  = tid & 15;
    const int ocg = tid >> 4;
    float acc[4][4] = {};

    #pragma unroll 4
    for (int ic = 0; ic < CIN; ic++) {
        float wk[4][K];
        #pragma unroll
        for (int m = 0; m < 4; m++)
            #pragma unroll
            for (int k = 0; k < K; k++)
                wk[m][k] = ws[(ic * COUT + ocg * 4 + m) * K + k];
        #pragma unroll
        for (int j = 0; j < 4; j++) {
            const float* xp = &xs[ic * XWP + S * (tg + 16 * j)];
            float xv[K];
            #pragma unroll
            for (int k = 0; k < K; k++) xv[k] = xp[k];
            #pragma unroll
            for (int m = 0; m < 4; m++)
                #pragma unroll
                for (int k = 0; k < K; k++)
                    acc[m][j] = fmaf(wk[m][k], xv[k], acc[m][j]);
        }
    }

    #pragma unroll
    for (int m = 0; m < 4; m++) {
        int oc = ocg * 4 + m;
        float bv = 0.f;
        if (BIAS) bv = bias[oc];
        #pragma unroll
        for (int j = 0; j < 4; j++) {
            int t = t0 + tg + 16 * j;
            size_t oi = ((size_t)b * COUT + oc) * Lout + t;
            float v = acc[m][j] + bv;
            if (RES) v += res[oi];
            if (POST) v = fmaxf(v, 0.f);
            out[oi] = v;
        }
    }
}

// ---------------------------------------------------------------------------
// ConvTranspose1d (R1-proven).
// ---------------------------------------------------------------------------
template <int CIN, int COUT, bool PRE, bool POST>
__global__ __launch_bounds__(COUT * 4) void tconv(
    const float* __restrict__ in, const float* __restrict__ w,
    const float* __restrict__ bias, float* __restrict__ out,
    int Lin, int Lout)
{
    constexpr int NT = COUT * 4;
    __shared__ __align__(16) float ws[CIN * COUT * 4];
    __shared__ float xs[CIN * 35];

    const int tid = threadIdx.x;
    const int b   = blockIdx.y;
    const int t0  = blockIdx.x * 64;
    const int xbase = (t0 >> 1) - 1;

    for (int i = tid; i < CIN * COUT * 4; i += NT) ws[i] = w[i];
    for (int i = tid; i < CIN * 34; i += NT) {
        int ic = i / 34;
        int l  = i - ic * 34;
        int pos = xbase + l;
        float v = (pos >= 0 && pos < Lin)
                      ? in[((size_t)b * CIN + ic) * Lin + pos] : 0.f;
        if (PRE) v = fmaxf(v, 0.f);
        xs[ic * 35 + l] = v;
    }
    __syncthreads();

    const int tg  = tid & 15;
    const int ocg = tid >> 4;
    float acc[4][4] = {};

    #pragma unroll 4
    for (int ic = 0; ic < CIN; ic++) {
        float wk[4][4];
        #pragma unroll
        for (int m = 0; m < 4; m++) {
            float4 f = ((const float4*)ws)[ic * COUT + ocg * 4 + m];
            wk[m][0] = f.x; wk[m][1] = f.y; wk[m][2] = f.z; wk[m][3] = f.w;
        }
        #pragma unroll
        for (int j = 0; j < 4; j++) {
            int tl = tg + 16 * j;
            #pragma unroll
            for (int k = 0; k < 4; k++) {
                int e = tl + 1 - k;
                if (!(e & 1)) {
                    float xv = xs[ic * 35 + (e >> 1) + 1];
                    #pragma unroll
                    for (int m = 0; m < 4; m++)
                        acc[m][j] = fmaf(wk[m][k], xv, acc[m][j]);
                }
            }
        }
    }

    #pragma unroll
    for (int m = 0; m < 4; m++) {
        int oc = ocg * 4 + m;
        float bv = bias[oc];
        #pragma unroll
        for (int j = 0; j < 4; j++) {
            int t = t0 + tg + 16 * j;
            float v = acc[m][j] + bv;
            if (POST) v = fmaxf(v, 0.f);
            out[((size_t)b * COUT + oc) * Lout + t] = v;
        }
    }
}

// ---------------------------------------------------------------------------
__global__ void enorm_kernel(const float* __restrict__ emb, float* __restrict__ en)
{
    int i = blockIdx.x * blockDim.x + threadIdx.x;
    if (i < 512) {
        float s = 0.f;
        #pragma unroll
        for (int d = 0; d < 64; d++) {
            float v = emb[i * 64 + d];
            s = fmaf(v, v, s);
        }
        en[i] = s;
    }
}

// ---------------------------------------------------------------------------
// VQ v3 (R6-proven).
// ---------------------------------------------------------------------------
__global__ __launch_bounds__(256) void vq_kernel(
    const float* __restrict__ z, const float* __restrict__ emb,
    const float* __restrict__ enorm, float* __restrict__ q)
{
    const int b    = blockIdx.y;
    const int wid  = threadIdx.x >> 5;
    const int lane = threadIdx.x & 31;
    const int t    = blockIdx.x * 32 + lane;

    float4 v[16];
    #pragma unroll
    for (int d = 0; d < 16; d++) {
        v[d].x = z[((size_t)b * 64 + 4 * d + 0) * 1024 + t];
        v[d].y = z[((size_t)b * 64 + 4 * d + 1) * 1024 + t];
        v[d].z = z[((size_t)b * 64 + 4 * d + 2) * 1024 + t];
        v[d].w = z[((size_t)b * 64 + 4 * d + 3) * 1024 + t];
    }

    __shared__ __align__(16) float es[64 * 64];
    __shared__ float rbest[8][32];
    __shared__ int   ridx[8][32];
    __shared__ int   win[32];

    float best = 3.4e38f;
    int bi = 0;

    for (int c0 = 0; c0 < 512; c0 += 64) {
        __syncthreads();
        for (int i = threadIdx.x; i < 1024; i += 256)
            ((float4*)es)[i] = ((const float4*)(emb + (size_t)c0 * 64))[i];
        __syncthreads();
        #pragma unroll
        for (int i = 0; i < 8; i++) {
            int cl = wid * 8 + i;
            const float4* e4 = (const float4*)&es[cl * 64];
            float s0 = 0.f, s1 = 0.f, s2 = 0.f, s3 = 0.f;
            #pragma unroll
            for (int d = 0; d < 16; d++) {
                float4 e = e4[d];
                s0 = fmaf(v[d].x, e.x, s0);
                s1 = fmaf(v[d].y, e.y, s1);
                s2 = fmaf(v[d].z, e.z, s2);
                s3 = fmaf(v[d].w, e.w, s3);
            }
            float dist = enorm[c0 + cl] - 2.f * ((s0 + s1) + (s2 + s3));
            int ci = c0 + cl;
            if (dist < best || (dist == best && ci < bi)) {
                best = dist; bi = ci;
            }
        }
    }

    rbest[wid][lane] = best;
    ridx[wid][lane]  = bi;
    __syncthreads();

    if (wid == 0) {
        float wb = rbest[0][lane];
        int   wi = ridx[0][lane];
        #pragma unroll
        for (int w = 1; w < 8; w++) {
            float ob = rbest[w][lane];
            int   oi = ridx[w][lane];
            if (ob < wb || (ob == wb && oi < wi)) { wb = ob; wi = oi; }
        }
        win[lane] = wi;
    }
    __syncthreads();

    const int widx = win[lane];
    #pragma unroll
    for (int i = 0; i < 8; i++) {
        int d = wid * 8 + i;
        q[((size_t)b * 64 + d) * 1024 + t] = __ldg(&emb[widx * 64 + d]);
    }
}

// ---------------------------------------------------------------------------
template <int CIN, int COUT, int K, int S, int P,
          bool PRE, bool POST, bool RES, bool BIAS, bool RED4>
static void launch_convk(const float* in, const float* w, const float* bias,
                         const float* res, const float* bias_in,
                         float* out, int Lin, int Lout)
{
    constexpr int TT = 64;
    constexpr int XW = S * TT + K - 1;
    constexpr int XWP = XW + 1;
    constexpr int NT = COUT * 4;
    size_t smem = (size_t)(CIN * COUT * K + CIN * XWP) * sizeof(float);
    auto kern = convk<CIN, COUT, K, S, P, PRE, POST, RES, BIAS, RED4>;
    cudaFuncSetAttribute(kern, cudaFuncAttributeMaxDynamicSharedMemorySize,
                         (int)smem);
    kern<<<dim3(Lout / TT, 16), NT, smem>>>(in, w, bias, res, bias_in, out,
                                            Lin, Lout);
}

template <bool PREVQ>
static void launch_resblock(const float* in, const float* w1, const float* w2,
                            const float* pqw, const float* pqb, float* out)
{
    size_t base = (size_t)(64 * 68 + 64 * 32 * 3 + 32 * 64 + 32 * 66);
    size_t smem = (base + (PREVQ ? (64 * 64 + 64 * 64) : 0)) * sizeof(float);
    auto kern = resblock<PREVQ>;
    cudaFuncSetAttribute(kern, cudaFuncAttributeMaxDynamicSharedMemorySize,
                         (int)smem);
    kern<<<dim3(16, 16), 256, smem>>>(in, w1, w2, pqw, pqb, out);
}

extern "C" void kernel_launch(void* const* d_in, const int* in_sizes, int n_in,
                              void* d_out, int out_size)
{
    (void)in_sizes; (void)n_in; (void)out_size;

    const float* x       = (const float*)d_in[0];
    const float* enc_w1  = (const float*)d_in[1];
    const float* enc_b1  = (const float*)d_in[2];
    const float* enc_w2  = (const float*)d_in[3];
    const float* enc_b2  = (const float*)d_in[4];
    const float* enc_w3  = (const float*)d_in[5];
    const float* enc_b3  = (const float*)d_in[6];
    const float* e_r0w1  = (const float*)d_in[7];
    const float* e_r0w2  = (const float*)d_in[8];
    const float* e_r1w1  = (const float*)d_in[9];
    const float* e_r1w2  = (const float*)d_in[10];
    const float* prevq_w = (const float*)d_in[11];
    const float* prevq_b = (const float*)d_in[12];
    const float* emb     = (const float*)d_in[13];
    const float* dec_w1  = (const float*)d_in[14];
    const float* dec_b1  = (const float*)d_in[15];
    const float* d_r0w1  = (const float*)d_in[16];
    const float* d_r0w2  = (const float*)d_in[17];
    const float* d_r1w1  = (const float*)d_in[18];
    const float* d_r1w2  = (const float*)d_in[19];
    const float* dect1_w = (const float*)d_in[20];
    const float* dect1_b = (const float*)d_in[21];
    const float* dect2_w = (const float*)d_in[22];
    const float* dect2_b = (const float*)d_in[23];
    float* out = (float*)d_out;

    float *A, *B, *C, *PP, *EN;
    __nv_bfloat16 *WHI, *WLO;
    cudaGetSymbolAddress((void**)&A,   g_A);
    cudaGetSymbolAddress((void**)&B,   g_B);
    cudaGetSymbolAddress((void**)&C,   g_C);
    cudaGetSymbolAddress((void**)&PP,  g_P);
    cudaGetSymbolAddress((void**)&WHI, g_Whi);
    cudaGetSymbolAddress((void**)&WLO, g_Wlo);
    cudaGetSymbolAddress((void**)&EN,  g_enorm);

    // enorm(1), wprep(2), conv1(3), conv2(4 = ncu target)
    enorm_kernel<<<1, 512>>>(emb, EN);
    wprep_kernel<<<384, 256>>>(enc_w1, WHI, WLO);

    conv1_mma<<<dim3(16, 16, 4), 128>>>(x, WHI, WLO, PP);

    launch_convk<32, 64, 4, 2, 1, false, true,  false, true,  true >(
        PP, enc_w2, enc_b2, nullptr, enc_b1, B, 2048, 1024);
    launch_convk<64, 64, 3, 1, 1, false, false, false, true,  false>(
        B, enc_w3, enc_b3, nullptr, nullptr, C, 1024, 1024);
    // Encoder residual stack; res1 carries the prevq epilogue -> B = z
    launch_resblock<false>(C, e_r0w1, e_r0w2, nullptr, nullptr, A);
    launch_resblock<true >(A, e_r1w1, e_r1w2, prevq_w, prevq_b, B);
    // VQ
    vq_kernel<<<dim3(32, 16), 256>>>(B, emb, EN, A);            // A = q
    // Decoder
    launch_convk<64, 64, 3, 1, 1, false, false, false, true,  false>(
        A, dec_w1, dec_b1, nullptr, nullptr, B, 1024, 1024);
    launch_resblock<false>(B, d_r0w1, d_r0w2, nullptr, nullptr, A);
    launch_resblock<false>(A, d_r1w1, d_r1w2, nullptr, nullptr, B);
    // Transposed convs
    tconv<64, 32, true,  true ><<<dim3(32, 16), 128>>>(B, dect1_w, dect1_b, C,   1024, 2048);
    tconv<32, 64, false, false><<<dim3(64, 16), 256>>>(C, dect2_w, dect2_b, out, 2048, 4096);
}